// round 2
// baseline (speedup 1.0000x reference)
#include <cuda_runtime.h>
#include <math.h>

#define B_    2
#define N_    2048
#define C_    384
#define NH    12
#define HD    32
#define BH    (B_*NH)      // 24
#define MTOK  (B_*N_)      // 4096

// ---------------- scratch (static device globals; no runtime alloc) -------
__device__ float g_qlin[MTOK * C_];         // 6 MB
__device__ float g_kvlin[MTOK * 2 * C_];    // 12 MB
__device__ float g_q[BH * N_ * HD];         // 6 MB  [bh][n][d]
__device__ float g_k[BH * N_ * HD];         // 6 MB
__device__ float g_v[BH * N_ * HD];         // 6 MB
__device__ float g_attn[MTOK * C_];         // 6 MB  [b][n][c]

// ---------------- generic fp32 GEMM:  Out[M,Nc] = X[M,K] @ W[Nc,K]^T + b ---
#define BM 64
#define BN 64
#define BK 16
#define PAD 68   // 64 + 4 floats pad: keeps float4 LDS aligned, kills bank conflicts

__global__ __launch_bounds__(256)
void gemm_bias(const float* __restrict__ X, const float* __restrict__ W,
               const float* __restrict__ bias, float* __restrict__ Out,
               int M, int Nc, int K)
{
    __shared__ __align__(16) float As[BK][PAD];
    __shared__ __align__(16) float Bs[BK][PAD];

    const int tid = threadIdx.x;
    const int tx  = tid & 15;     // 0..15 -> output cols
    const int ty  = tid >> 4;     // 0..15 -> output rows
    const int m0  = blockIdx.y * BM;
    const int n0  = blockIdx.x * BN;

    // loader mapping: 256 threads load 64 rows x 16 k (float4 each)
    const int lrow = tid >> 2;          // 0..63
    const int lk4  = (tid & 3) * 4;     // 0,4,8,12
    const float* Xp = X + (size_t)(m0 + lrow) * K + lk4;
    const float* Wp = W + (size_t)(n0 + lrow) * K + lk4;

    float acc[4][4] = {};

    for (int k0 = 0; k0 < K; k0 += BK) {
        float4 xa = *(const float4*)(Xp + k0);
        float4 wa = *(const float4*)(Wp + k0);
        __syncthreads();
        As[lk4 + 0][lrow] = xa.x; As[lk4 + 1][lrow] = xa.y;
        As[lk4 + 2][lrow] = xa.z; As[lk4 + 3][lrow] = xa.w;
        Bs[lk4 + 0][lrow] = wa.x; Bs[lk4 + 1][lrow] = wa.y;
        Bs[lk4 + 2][lrow] = wa.z; Bs[lk4 + 3][lrow] = wa.w;
        __syncthreads();

        #pragma unroll
        for (int kk = 0; kk < BK; kk++) {
            float4 a = *(const float4*)&As[kk][ty * 4];
            float4 b = *(const float4*)&Bs[kk][tx * 4];
            float av[4] = {a.x, a.y, a.z, a.w};
            float bv[4] = {b.x, b.y, b.z, b.w};
            #pragma unroll
            for (int i = 0; i < 4; i++)
                #pragma unroll
                for (int j = 0; j < 4; j++)
                    acc[i][j] = fmaf(av[i], bv[j], acc[i][j]);
        }
    }

    float4 bb = *(const float4*)&bias[n0 + tx * 4];
    float bvv[4] = {bb.x, bb.y, bb.z, bb.w};
    #pragma unroll
    for (int i = 0; i < 4; i++) {
        float4 o;
        o.x = acc[i][0] + bvv[0];
        o.y = acc[i][1] + bvv[1];
        o.z = acc[i][2] + bvv[2];
        o.w = acc[i][3] + bvv[3];
        *(float4*)&Out[(size_t)(m0 + ty * 4 + i) * Nc + n0 + tx * 4] = o;
    }
}

// ---------------- arrange: l2norm q/k, +emb, *scale, scatter to [bh][n][d] --
__global__ __launch_bounds__(256)
void arrange_kernel(const float* __restrict__ qemb, const float* __restrict__ temp)
{
    int gw   = (blockIdx.x * 256 + threadIdx.x) >> 5;   // one warp per (b,n,h)
    int lane = threadIdx.x & 31;
    if (gw >= B_ * N_ * NH) return;
    int h = gw % NH;
    int n = (gw / NH) % N_;
    int b = gw / (NH * N_);
    int tok = b * N_ + n;

    // q
    float qv = g_qlin[(size_t)tok * C_ + h * HD + lane];
    float ss = qv * qv;
    #pragma unroll
    for (int off = 16; off; off >>= 1) ss += __shfl_xor_sync(0xffffffffu, ss, off);
    float dn = fmaxf(sqrtf(ss), 1e-12f);
    float scale = log1pf(expf(temp[h])) * logf((float)N_);
    qv = (qv / dn + qemb[h * HD + lane]) * scale;
    g_q[((size_t)(b * NH + h) * N_ + n) * HD + lane] = qv;

    // k
    float kv = g_kvlin[(size_t)tok * 2 * C_ + h * HD + lane];
    ss = kv * kv;
    #pragma unroll
    for (int off = 16; off; off >>= 1) ss += __shfl_xor_sync(0xffffffffu, ss, off);
    dn = fmaxf(sqrtf(ss), 1e-12f);
    g_k[((size_t)(b * NH + h) * N_ + n) * HD + lane] = kv / dn;

    // v (straight copy into attention layout)
    g_v[((size_t)(b * NH + h) * N_ + n) * HD + lane] =
        g_kvlin[(size_t)tok * 2 * C_ + C_ + h * HD + lane];
}

// ---------------- flash attention: 1 query/thread, K/V tiles of 32 ---------
__global__ __launch_bounds__(128)
void attn_kernel(const float* __restrict__ pos_bias)
{
    __shared__ __align__(16) float Ks[32][HD];
    __shared__ __align__(16) float Vs[32][HD];
    __shared__ float bs[32];

    const int bh  = blockIdx.y;
    const int h   = bh % NH;
    const int b   = bh / NH;
    const int tid = threadIdx.x;
    const int qrow = blockIdx.x * 128 + tid;

    const float* Qp = g_q + ((size_t)bh * N_ + qrow) * HD;
    float4 qv[8];
    #pragma unroll
    for (int i = 0; i < 8; i++) qv[i] = ((const float4*)Qp)[i];

    float acc[HD];
    #pragma unroll
    for (int d = 0; d < HD; d++) acc[d] = 0.f;
    float m = -1e30f, l = 0.f;

    const float4* Kbase = (const float4*)(g_k + (size_t)bh * N_ * HD);
    const float4* Vbase = (const float4*)(g_v + (size_t)bh * N_ * HD);
    const float*  pb    = pos_bias + h * N_;

    for (int t = 0; t < N_ / 32; t++) {
        __syncthreads();
        const float4* ks = Kbase + t * 256;   // 32 keys * 8 float4
        const float4* vs = Vbase + t * 256;
        ((float4*)Ks)[tid]       = ks[tid];
        ((float4*)Ks)[tid + 128] = ks[tid + 128];
        ((float4*)Vs)[tid]       = vs[tid];
        ((float4*)Vs)[tid + 128] = vs[tid + 128];
        if (tid < 32) bs[tid] = pb[t * 32 + tid];
        __syncthreads();

        float s[32];
        #pragma unroll
        for (int j = 0; j < 32; j++) {
            const float4* kr = (const float4*)Ks[j];
            float sum = bs[j];
            #pragma unroll
            for (int i = 0; i < 8; i++) {
                float4 k4 = kr[i];
                sum = fmaf(qv[i].x, k4.x, sum);
                sum = fmaf(qv[i].y, k4.y, sum);
                sum = fmaf(qv[i].z, k4.z, sum);
                sum = fmaf(qv[i].w, k4.w, sum);
            }
            s[j] = sum;
        }

        float tmax = s[0];
        #pragma unroll
        for (int j = 1; j < 32; j++) tmax = fmaxf(tmax, s[j]);
        float nm    = fmaxf(m, tmax);
        float alpha = __expf(m - nm);
        float lsum  = 0.f;
        #pragma unroll
        for (int j = 0; j < 32; j++) { float p = __expf(s[j] - nm); s[j] = p; lsum += p; }
        l = l * alpha + lsum;
        m = nm;

        #pragma unroll
        for (int d = 0; d < HD; d++) acc[d] *= alpha;
        #pragma unroll
        for (int j = 0; j < 32; j++) {
            const float4* vr = (const float4*)Vs[j];
            float p = s[j];
            #pragma unroll
            for (int i = 0; i < 8; i++) {
                float4 v4 = vr[i];
                acc[4*i + 0] = fmaf(p, v4.x, acc[4*i + 0]);
                acc[4*i + 1] = fmaf(p, v4.y, acc[4*i + 1]);
                acc[4*i + 2] = fmaf(p, v4.z, acc[4*i + 2]);
                acc[4*i + 3] = fmaf(p, v4.w, acc[4*i + 3]);
            }
        }
    }

    float inv = 1.f / l;
    float* op = g_attn + ((size_t)(b * N_ + qrow)) * C_ + h * HD;
    #pragma unroll
    for (int i = 0; i < 8; i++) {
        float4 o;
        o.x = acc[4*i + 0] * inv;
        o.y = acc[4*i + 1] * inv;
        o.z = acc[4*i + 2] * inv;
        o.w = acc[4*i + 3] * inv;
        ((float4*)op)[i] = o;
    }
}

// ---------------------------------------------------------------------------
extern "C" void kernel_launch(void* const* d_in, const int* in_sizes, int n_in,
                              void* d_out, int out_size)
{
    (void)in_sizes; (void)n_in; (void)out_size;
    const float* x        = (const float*)d_in[0];
    const float* q_w      = (const float*)d_in[1];
    const float* q_b      = (const float*)d_in[2];
    const float* kv_w     = (const float*)d_in[3];
    const float* kv_b     = (const float*)d_in[4];
    const float* qemb     = (const float*)d_in[5];
    const float* temp     = (const float*)d_in[6];
    const float* pos_bias = (const float*)d_in[7];
    const float* proj_w   = (const float*)d_in[8];
    const float* proj_b   = (const float*)d_in[9];
    float* out = (float*)d_out;

    float *qlin, *kvlin, *attn;
    cudaGetSymbolAddress((void**)&qlin,  g_qlin);
    cudaGetSymbolAddress((void**)&kvlin, g_kvlin);
    cudaGetSymbolAddress((void**)&attn,  g_attn);

    // q projection: [4096,384] @ [384,384]^T
    gemm_bias<<<dim3(C_ / BN, MTOK / BM), 256>>>(x, q_w, q_b, qlin, MTOK, C_, C_);
    // kv projection: [4096,384] @ [768,384]^T
    gemm_bias<<<dim3(2 * C_ / BN, MTOK / BM), 256>>>(x, kv_w, kv_b, kvlin, MTOK, 2 * C_, C_);
    // normalize + embed + scale + scatter
    arrange_kernel<<<(B_ * N_ * NH * 32) / 256, 256>>>(qemb, temp);
    // attention
    attn_kernel<<<dim3(N_ / 128, BH), 128>>>(pos_bias);
    // output projection
    gemm_bias<<<dim3(C_ / BN, MTOK / BM), 256>>>(attn, proj_w, proj_b, out, MTOK, C_, C_);
}